// round 13
// baseline (speedup 1.0000x reference)
#include <cuda_runtime.h>
#include <cstdint>

#define NNODES  100000
#define NEDGES  1600000
#define NGRAPHS 64
#define EPS     1e-5f
#define NCHUNK  ((NNODES + 511) / 512)   // 196

typedef unsigned long long u64;

// ---------------- device scratch ----------------
__device__ int   g_deg [NNODES];
__device__ int   g_roff[NNODES];
__device__ int   g_cur [NNODES];
__device__ int   g_csr [NEDGES];
__device__ int   g_bsum [256];
__device__ __align__(16) float g_h1[NNODES * 32];
__device__ __align__(16) float g_h2[NNODES * 64];
__device__ __align__(16) float g_h3[(size_t)NNODES * 128];
__device__ __align__(16) float g_stats[448];   // L1 sum@0 sq@32 | L2 sum@64 sq@128 | L3 sum@192 sq@320
__device__ __align__(16) float g_pool[NGRAPHS * 128];
__device__ float g_cntg[NGRAPHS];

// ---------------- helpers ----------------
__device__ __forceinline__ u64 ffma2(u64 a, u64 b, u64 c) {
    u64 d;
    asm("fma.rn.f32x2 %0, %1, %2, %3;" : "=l"(d) : "l"(a), "l"(b), "l"(c));
    return d;
}
__device__ __forceinline__ float2 unpack2(u64 v) {
    float2 r;
    asm("mov.b64 {%0, %1}, %2;" : "=f"(r.x), "=f"(r.y) : "l"(v));
    return r;
}
__device__ __forceinline__ void red_f32(float* addr, float v) {
    asm volatile("red.global.add.f32 [%0], %1;" :: "l"(addr), "f"(v) : "memory");
}
__device__ __forceinline__ void red_add_v4(float* addr, float a, float b, float c, float d) {
    asm volatile("red.global.add.v4.f32 [%0], {%1,%2,%3,%4};"
                 :: "l"(addr), "f"(a), "f"(b), "f"(c), "f"(d) : "memory");
}

// ---------------- CSR build (+ per-graph node counts) ----------------
__global__ void k_deg(const int* __restrict__ dst, const int* __restrict__ batch, int e) {
    int i = blockIdx.x * blockDim.x + threadIdx.x;
    if (i < e) atomicAdd(&g_deg[dst[i]], 1);
    if (i < NNODES) {
        int g = batch[i];
        unsigned act = __activemask();
        unsigned mask = __match_any_sync(act, g);
        int leader = __ffs(mask) - 1;
        if ((threadIdx.x & 31) == leader) atomicAdd(&g_cntg[g], (float)__popc(mask));
    }
}

__global__ void k_chunks() {
    __shared__ int s[512];
    int tid = threadIdx.x;
    int i = blockIdx.x * 512 + tid;
    s[tid] = (i < NNODES) ? g_deg[i] : 0;
    __syncthreads();
    for (int off = 256; off > 0; off >>= 1) {
        if (tid < off) s[tid] += s[tid + off];
        __syncthreads();
    }
    if (tid == 0) g_bsum[blockIdx.x] = s[0];
}

__global__ void k_scan() {
    __shared__ int sb[256];
    __shared__ int s[512];
    int tid = threadIdx.x;
    if (tid < 256) sb[tid] = (tid < NCHUNK) ? g_bsum[tid] : 0;
    int i = blockIdx.x * 512 + tid;
    int v = (i < NNODES) ? g_deg[i] : 0;
    s[tid] = v;
    __syncthreads();
    for (int off = 1; off < 256; off <<= 1) {
        int t = 0;
        if (tid < 256 && tid >= off) t = sb[tid - off];
        __syncthreads();
        if (tid < 256) sb[tid] += t;
        __syncthreads();
    }
    for (int off = 1; off < 512; off <<= 1) {
        int t = (tid >= off) ? s[tid - off] : 0;
        __syncthreads();
        s[tid] += t;
        __syncthreads();
    }
    if (i < NNODES) {
        int base = (blockIdx.x > 0) ? sb[blockIdx.x - 1] : 0;
        int r = base + s[tid] - v;
        g_roff[i] = r;
        g_cur[i]  = r;
    }
}

__global__ void k_fill(const int* __restrict__ src, const int* __restrict__ dst, int e) {
    int i = blockIdx.x * blockDim.x + threadIdx.x;
    if (i < e) {
        int d = dst[i];
        int pos = atomicAdd(&g_cur[d], 1);
        g_csr[pos] = src[i];
    }
}

// ---------------- layer 1: 2 -> 32, thread/node, stats fused, pipelined gather ----------------
__global__ __launch_bounds__(256) void k_layer1(const float* __restrict__ x,
                                                const float* __restrict__ Wl,
                                                const float* __restrict__ bl,
                                                const float* __restrict__ Wr,
                                                float* __restrict__ gsum, float* __restrict__ gsq) {
    __shared__ float sWl[64], sWr[64], sbl[32];
    __shared__ float sRed[512];
    int tid = threadIdx.x, lane = tid & 31, w = tid >> 5;
    if (tid < 64) { sWl[tid] = Wl[tid]; sWr[tid] = Wr[tid]; }
    if (tid < 32) sbl[tid] = bl[tid];
    __syncthreads();
    int n = blockIdx.x * 256 + tid;
    bool active = (n < NNODES);
    const float2* x2 = (const float2*)x;
    float a0 = 0.f, a1 = 0.f;
    float2 xv = make_float2(0.f, 0.f);
    if (active) {
        int st = g_roff[n], d = g_deg[n];
        int k = 0;
        int si[8];
        if (d >= 8) {
#pragma unroll
            for (int j = 0; j < 8; j++) si[j] = g_csr[st + j];
        }
        while (k + 8 <= d) {
            int kn = k + 8;
            bool more = (kn + 8 <= d);
            int sn[8];
#pragma unroll
            for (int j = 0; j < 8; j++) sn[j] = more ? g_csr[st + kn + j] : 0;
            float2 v[8];
#pragma unroll
            for (int j = 0; j < 8; j++) v[j] = x2[si[j]];
#pragma unroll
            for (int j = 0; j < 8; j++) { a0 += v[j].x; a1 += v[j].y; }
#pragma unroll
            for (int j = 0; j < 8; j++) si[j] = sn[j];
            k = kn;
        }
        for (; k < d; ++k) { float2 v = x2[g_csr[st + k]]; a0 += v.x; a1 += v.y; }
        float inv = 1.f / (float)max(d, 1);
        a0 *= inv; a1 *= inv;
        xv = x2[n];
    }
    float z[32];
#pragma unroll
    for (int j = 0; j < 32; j++)
        z[j] = active ? (sbl[j] + a0 * sWl[j] + a1 * sWl[32 + j] + xv.x * sWr[j] + xv.y * sWr[32 + j]) : 0.f;
    if (active) {
        float* outp = &g_h1[n * 32];
#pragma unroll
        for (int j = 0; j < 32; j += 4)
            *(float4*)&outp[j] = make_float4(z[j], z[j + 1], z[j + 2], z[j + 3]);
    }
    float ws = 0.f, wq = 0.f;
#pragma unroll
    for (int c = 0; c < 32; c++) {
        float s = z[c];
        float q = z[c] * z[c];
#pragma unroll
        for (int o = 16; o; o >>= 1) {
            s += __shfl_xor_sync(0xffffffffu, s, o);
            q += __shfl_xor_sync(0xffffffffu, q, o);
        }
        if (lane == c) { ws = s; wq = q; }
    }
    sRed[w * 64 + lane]      = ws;
    sRed[w * 64 + 32 + lane] = wq;
    __syncthreads();
    if (tid < 64) {
        int c = tid & 31;
        int off = (tid >= 32) ? 32 : 0;
        float a = 0.f;
#pragma unroll
        for (int w2 = 0; w2 < 8; w2++) a += sRed[w2 * 64 + off + c];
        red_f32((tid >= 32) ? &gsq[c] : &gsum[c], a);
    }
}

// ---------------- layer 2: 32 -> 64; BN1+relu fused; duplicated smem operands ----------------
__global__ __launch_bounds__(256) void k_layer2(const float* __restrict__ Wl,
                                                const float* __restrict__ bl,
                                                const float* __restrict__ Wr,
                                                const float* __restrict__ st1,   // sum@0, sq@32
                                                const float* __restrict__ gam, const float* __restrict__ bet,
                                                float* __restrict__ gsum, float* __restrict__ gsq) {
    __shared__ float sWl[2048], sWr[2048], sbl[64];
    __shared__ float sSc[32], sSh[32];
    __shared__ float sA[64 * 64];   // row r: [r*64 + 2*i] = {a_i, a_i}
    __shared__ float sX[64 * 64];   // row r: [r*64 + 2*i] = {x_i, x_i}
    int tid = threadIdx.x, lane = tid & 31, w = tid >> 5;
    for (int i = tid; i < 2048; i += 256) { sWl[i] = Wl[i]; sWr[i] = Wr[i]; }
    if (tid < 64) sbl[tid] = bl[tid];
    if (tid < 32) {
        float mean = st1[tid] * (1.f / NNODES);
        float var  = st1[32 + tid] * (1.f / NNODES) - mean * mean;
        float sc = gam[tid] * rsqrtf(var + EPS);
        sSc[tid] = sc;
        sSh[tid] = bet[tid] - mean * sc;
    }
    __syncthreads();
    float sc = sSc[lane], sh = sSh[lane];
    int base = blockIdx.x * 64;
    for (int r = 0; r < 8; r++) {
        int rr = w * 8 + r;
        int node = base + rr;
        float av = 0.f, xvv = 0.f;
        if (node < NNODES) {
            int st = g_roff[node], d = g_deg[node];
            float acc = 0.f;
            int k = 0;
            int si[8];
            if (d >= 8) {
#pragma unroll
                for (int j = 0; j < 8; j++) si[j] = g_csr[st + j];
            }
            while (k + 8 <= d) {
                int kn = k + 8;
                bool more = (kn + 8 <= d);
                int sn[8];
#pragma unroll
                for (int j = 0; j < 8; j++) sn[j] = more ? g_csr[st + kn + j] : 0;
                float v[8];
#pragma unroll
                for (int j = 0; j < 8; j++) v[j] = g_h1[si[j] * 32 + lane];
#pragma unroll
                for (int j = 0; j < 8; j++) acc += fmaxf(fmaf(v[j], sc, sh), 0.f);
#pragma unroll
                for (int j = 0; j < 8; j++) si[j] = sn[j];
                k = kn;
            }
            for (; k < d; ++k) acc += fmaxf(fmaf(g_h1[g_csr[st + k] * 32 + lane], sc, sh), 0.f);
            av  = acc * (1.f / (float)max(d, 1));
            xvv = fmaxf(fmaf(g_h1[node * 32 + lane], sc, sh), 0.f);
        }
        *(float2*)&sA[rr * 64 + 2 * lane] = make_float2(av, av);
        *(float2*)&sX[rr * 64 + 2 * lane] = make_float2(xvv, xvv);
    }
    __syncthreads();
    u64 acc[8];
    {
        u64 b = *(const u64*)&sbl[2 * lane];
#pragma unroll
        for (int r = 0; r < 8; r++) acc[r] = b;
    }
#pragma unroll 4
    for (int i = 0; i < 32; i++) {
        u64 wl = *(const u64*)&sWl[i * 64 + 2 * lane];
        u64 wr = *(const u64*)&sWr[i * 64 + 2 * lane];
#pragma unroll
        for (int r = 0; r < 8; r++) {
            u64 A = *(const u64*)&sA[(w * 8 + r) * 64 + 2 * i];
            u64 X = *(const u64*)&sX[(w * 8 + r) * 64 + 2 * i];
            acc[r] = ffma2(A, wl, acc[r]);
            acc[r] = ffma2(X, wr, acc[r]);
        }
    }
    float s0 = 0.f, s1 = 0.f, q0 = 0.f, q1 = 0.f;
#pragma unroll
    for (int r = 0; r < 8; r++) {
        int node = base + w * 8 + r;
        if (node < NNODES) {
            float2 v = unpack2(acc[r]);
            *(float2*)&g_h2[node * 64 + 2 * lane] = v;
            s0 += v.x; s1 += v.y; q0 += v.x * v.x; q1 += v.y * v.y;
        }
    }
    __syncthreads();
    float* sRed = sA;
    sRed[w * 128 + 2 * lane]     = s0;
    sRed[w * 128 + 2 * lane + 1] = s1;
    sRed[w * 128 + 64 + 2 * lane]     = q0;
    sRed[w * 128 + 64 + 2 * lane + 1] = q1;
    __syncthreads();
    if (tid < 128) {
        int c = tid & 63;
        int off = (tid >= 64) ? 64 : 0;
        float a = 0.f;
#pragma unroll
        for (int w2 = 0; w2 < 8; w2++) a += sRed[w2 * 128 + off + c];
        red_f32((tid >= 64) ? &gsq[c] : &gsum[c], a);
    }
}

// ---------------- layer 3: 64 -> 128; 128 thr/block; duplicated smem operands ----------------
__global__ __launch_bounds__(128) void k_layer3(const float* __restrict__ Wl,
                                                const float* __restrict__ bl,
                                                const float* __restrict__ Wr,
                                                const float* __restrict__ st2,   // sum@0, sq@64
                                                const float* __restrict__ gam, const float* __restrict__ bet,
                                                float* __restrict__ gsum, float* __restrict__ gsq) {
    __shared__ float sA[32 * 128];   // row r: [r*128 + 2*i] = {a_i, a_i}
    __shared__ float sX[32 * 128];   // row r: [r*128 + 2*i] = {x_i, x_i}
    __shared__ float sSc[64], sSh[64];
    int tid = threadIdx.x, lane = tid & 31, w = tid >> 5;   // 4 warps
    if (tid < 64) {
        float mean = st2[tid] * (1.f / NNODES);
        float var  = st2[64 + tid] * (1.f / NNODES) - mean * mean;
        float sc = gam[tid] * rsqrtf(var + EPS);
        sSc[tid] = sc;
        sSh[tid] = bet[tid] - mean * sc;
    }
    __syncthreads();
    float sc0 = sSc[2 * lane], sc1 = sSc[2 * lane + 1];
    float sh0 = sSh[2 * lane], sh1 = sSh[2 * lane + 1];
    int base = blockIdx.x * 32;
    const float2* h2v = (const float2*)g_h2;
    for (int r = 0; r < 8; r++) {
        int rr = w * 8 + r;
        int node = base + rr;
        float a0m = 0.f, a1m = 0.f, x0 = 0.f, x1 = 0.f;
        if (node < NNODES) {
            int st = g_roff[node], d = g_deg[node];
            float a0 = 0.f, a1 = 0.f;
            int k = 0;
            int si[8];
            if (d >= 8) {
#pragma unroll
                for (int j = 0; j < 8; j++) si[j] = g_csr[st + j];
            }
            while (k + 8 <= d) {
                int kn = k + 8;
                bool more = (kn + 8 <= d);
                int sn[8];
#pragma unroll
                for (int j = 0; j < 8; j++) sn[j] = more ? g_csr[st + kn + j] : 0;
                float2 v[8];
#pragma unroll
                for (int j = 0; j < 8; j++) v[j] = h2v[si[j] * 32 + lane];
#pragma unroll
                for (int j = 0; j < 8; j++) {
                    a0 += fmaxf(fmaf(v[j].x, sc0, sh0), 0.f);
                    a1 += fmaxf(fmaf(v[j].y, sc1, sh1), 0.f);
                }
#pragma unroll
                for (int j = 0; j < 8; j++) si[j] = sn[j];
                k = kn;
            }
            for (; k < d; ++k) {
                float2 v = h2v[g_csr[st + k] * 32 + lane];
                a0 += fmaxf(fmaf(v.x, sc0, sh0), 0.f);
                a1 += fmaxf(fmaf(v.y, sc1, sh1), 0.f);
            }
            float inv = 1.f / (float)max(d, 1);
            float2 hx = h2v[node * 32 + lane];
            a0m = a0 * inv;
            a1m = a1 * inv;
            x0 = fmaxf(fmaf(hx.x, sc0, sh0), 0.f);
            x1 = fmaxf(fmaf(hx.y, sc1, sh1), 0.f);
        }
        *(float4*)&sA[rr * 128 + 4 * lane] = make_float4(a0m, a0m, a1m, a1m);
        *(float4*)&sX[rr * 128 + 4 * lane] = make_float4(x0, x0, x1, x1);
    }
    __syncthreads();
    const ulonglong2* Wl2 = (const ulonglong2*)Wl;
    const ulonglong2* Wr2 = (const ulonglong2*)Wr;
    u64 a01[8], a23[8];
    {
        ulonglong2 b2 = __ldg((const ulonglong2*)bl + lane);
#pragma unroll
        for (int r = 0; r < 8; r++) { a01[r] = b2.x; a23[r] = b2.y; }
    }
#pragma unroll 2
    for (int i = 0; i < 64; i++) {
        ulonglong2 wl = __ldg(Wl2 + i * 32 + lane);
        ulonglong2 wr = __ldg(Wr2 + i * 32 + lane);
#pragma unroll
        for (int r = 0; r < 8; r++) {
            u64 A = *(const u64*)&sA[(w * 8 + r) * 128 + 2 * i];
            u64 X = *(const u64*)&sX[(w * 8 + r) * 128 + 2 * i];
            a01[r] = ffma2(A, wl.x, a01[r]);
            a23[r] = ffma2(A, wl.y, a23[r]);
            a01[r] = ffma2(X, wr.x, a01[r]);
            a23[r] = ffma2(X, wr.y, a23[r]);
        }
    }
    float s[4] = {0.f, 0.f, 0.f, 0.f}, q[4] = {0.f, 0.f, 0.f, 0.f};
#pragma unroll
    for (int r = 0; r < 8; r++) {
        int node = base + w * 8 + r;
        if (node < NNODES) {
            float2 v01 = unpack2(a01[r]);
            float2 v23 = unpack2(a23[r]);
            *(float4*)&g_h3[(size_t)node * 128 + 4 * lane] = make_float4(v01.x, v01.y, v23.x, v23.y);
            s[0] += v01.x; s[1] += v01.y; s[2] += v23.x; s[3] += v23.y;
            q[0] += v01.x * v01.x; q[1] += v01.y * v01.y; q[2] += v23.x * v23.x; q[3] += v23.y * v23.y;
        }
    }
    __syncthreads();
    float* sRed = sA;   // 4 warps × 256 floats = 1024 <= 4096
#pragma unroll
    for (int k = 0; k < 4; k++) {
        sRed[w * 256 + 4 * lane + k]       = s[k];
        sRed[w * 256 + 128 + 4 * lane + k] = q[k];
    }
    __syncthreads();
    {
        int c = tid;
        float a = 0.f, b = 0.f;
#pragma unroll
        for (int w2 = 0; w2 < 4; w2++) {
            a += sRed[w2 * 256 + c];
            b += sRed[w2 * 256 + 128 + c];
        }
        red_f32(&gsum[c], a);
        red_f32(&gsq[c], b);
    }
}

// ---------------- fused finalize3 + bn + relu + pool ----------------
__global__ __launch_bounds__(256) void k_bnpool(const int* __restrict__ batch,
                                                const float* __restrict__ gsum, const float* __restrict__ gsq,
                                                const float* __restrict__ gam, const float* __restrict__ bet) {
    __shared__ float ssc[128], ssh[128];
    int tid = threadIdx.x;
    if (tid < 128) {
        float mean = gsum[tid] * (1.f / NNODES);
        float var  = gsq[tid] * (1.f / NNODES) - mean * mean;
        float sc = gam[tid] * rsqrtf(var + EPS);
        ssc[tid] = sc;
        ssh[tid] = bet[tid] - mean * sc;
    }
    __syncthreads();
    int idx = blockIdx.x * 256 + tid;
    int row = idx >> 5, c4 = idx & 31;
    int c = c4 * 4;
    float4 v = ((const float4*)g_h3)[idx];
    float4 sc = *(const float4*)&ssc[c];
    float4 sh = *(const float4*)&ssh[c];
    v.x = fmaxf(v.x * sc.x + sh.x, 0.f);
    v.y = fmaxf(v.y * sc.y + sh.y, 0.f);
    v.z = fmaxf(v.z * sc.z + sh.z, 0.f);
    v.w = fmaxf(v.w * sc.w + sh.w, 0.f);
    int g = batch[row];
    red_add_v4(&g_pool[g * 128 + c], v.x, v.y, v.z, v.w);
}

// ---------------- head MLP ----------------
__global__ void k_mlp(const float* __restrict__ Wf1, const float* __restrict__ bf1,
                      const float* __restrict__ Wf2, const float* __restrict__ bf2,
                      float* __restrict__ out) {
    __shared__ float sp[128];
    __shared__ float sh[64];
    int g = blockIdx.x, tid = threadIdx.x;
    float inv = 1.f / fmaxf(g_cntg[g], 1.f);
    sp[tid] = g_pool[g * 128 + tid] * inv;
    __syncthreads();
    if (tid < 64) {
        float acc = bf1[tid];
#pragma unroll 8
        for (int i = 0; i < 128; i++) acc += sp[i] * Wf1[i * 64 + tid];
        acc = fmaxf(acc, 0.f);
        sh[tid] = acc * Wf2[tid];
    }
    __syncthreads();
    if (tid < 32) {
        float v = sh[tid] + sh[tid + 32];
        for (int o = 16; o; o >>= 1) v += __shfl_down_sync(0xffffffffu, v, o);
        if (tid == 0) out[g] = v + bf2[0];
    }
}

// ---------------- launch ----------------
extern "C" void kernel_launch(void* const* d_in, const int* in_sizes, int n_in,
                              void* d_out, int out_size) {
    const float* x     = (const float*)d_in[0];
    const int*   ei    = (const int*)d_in[1];
    const int*   batch = (const int*)d_in[2];
    const float* Wl1 = (const float*)d_in[3];
    const float* bl1 = (const float*)d_in[4];
    const float* Wr1 = (const float*)d_in[5];
    const float* g1  = (const float*)d_in[6];
    const float* be1 = (const float*)d_in[7];
    const float* Wl2 = (const float*)d_in[8];
    const float* bl2 = (const float*)d_in[9];
    const float* Wr2 = (const float*)d_in[10];
    const float* g2  = (const float*)d_in[11];
    const float* be2 = (const float*)d_in[12];
    const float* Wl3 = (const float*)d_in[13];
    const float* bl3 = (const float*)d_in[14];
    const float* Wr3 = (const float*)d_in[15];
    const float* g3  = (const float*)d_in[16];
    const float* be3 = (const float*)d_in[17];
    const float* Wf1 = (const float*)d_in[18];
    const float* bf1 = (const float*)d_in[19];
    const float* Wf2 = (const float*)d_in[20];
    const float* bf2 = (const float*)d_in[21];

    int E = in_sizes[1] / 2;
    const int* src = ei;
    const int* dst = ei + E;

    void *p_stats, *p_deg, *p_pool, *p_cnt;
    cudaGetSymbolAddress(&p_stats, g_stats);
    cudaGetSymbolAddress(&p_deg,   g_deg);
    cudaGetSymbolAddress(&p_pool,  g_pool);
    cudaGetSymbolAddress(&p_cnt,   g_cntg);
    float* st = (float*)p_stats;

    int eb = (E + 255) / 256;
    const int NB = (NNODES + 255) / 256;   // 391
    const int GB2 = (NNODES + 63) / 64;    // 1563
    const int GB3 = (NNODES + 31) / 32;    // 3125 (128-thread blocks)

    cudaMemsetAsync(p_deg,   0, NNODES * sizeof(int));
    cudaMemsetAsync(p_stats, 0, 448 * sizeof(float));
    cudaMemsetAsync(p_pool,  0, NGRAPHS * 128 * sizeof(float));
    cudaMemsetAsync(p_cnt,   0, NGRAPHS * sizeof(float));

    k_deg<<<eb, 256>>>(dst, batch, E);
    k_chunks<<<NCHUNK, 512>>>();
    k_scan<<<NCHUNK, 512>>>();
    k_fill<<<eb, 256>>>(src, dst, E);

    // layer 1 (stats fused, pipelined gather)
    k_layer1<<<NB, 256>>>(x, Wl1, bl1, Wr1, st + 0, st + 32);

    // layer 2 (BN1+relu fused, duplicated smem operands, stats fused)
    k_layer2<<<GB2, 256>>>(Wl2, bl2, Wr2, st + 0, g1, be1, st + 64, st + 128);

    // layer 3 (BN2+relu fused, duplicated smem operands, 8 rows/warp)
    k_layer3<<<GB3, 128>>>(Wl3, bl3, Wr3, st + 64, g2, be2, st + 192, st + 320);

    // fused bn3 + relu + pool, then head
    k_bnpool<<<(NNODES * 32) / 256, 256>>>(batch, st + 192, st + 320, g3, be3);
    k_mlp<<<NGRAPHS, 128>>>(Wf1, bf1, Wf2, bf2, (float*)d_out);
}

// round 14
// speedup vs baseline: 1.4098x; 1.4098x over previous
#include <cuda_runtime.h>
#include <cstdint>

#define NNODES  100000
#define NEDGES  1600000
#define NGRAPHS 64
#define EPS     1e-5f
#define NCHUNK  ((NNODES + 511) / 512)   // 196

typedef unsigned long long u64;

// ---------------- device scratch ----------------
__device__ int   g_deg [NNODES];
__device__ int   g_roff[NNODES];
__device__ int   g_cur [NNODES];
__device__ int   g_csr [NEDGES];
__device__ int   g_bsum [256];
__device__ __align__(16) float g_h1[NNODES * 32];
__device__ __align__(16) float g_h2[NNODES * 64];
__device__ __align__(16) float g_h3[(size_t)NNODES * 128];
__device__ __align__(16) float g_stats[448];   // L1 sum@0 sq@32 | L2 sum@64 sq@128 | L3 sum@192 sq@320
__device__ __align__(16) float g_pool[NGRAPHS * 128];
__device__ float g_cntg[NGRAPHS];

// ---------------- helpers ----------------
__device__ __forceinline__ u64 ffma2(u64 a, u64 b, u64 c) {
    u64 d;
    asm("fma.rn.f32x2 %0, %1, %2, %3;" : "=l"(d) : "l"(a), "l"(b), "l"(c));
    return d;
}
__device__ __forceinline__ u64 pack2(float lo, float hi) {
    u64 r;
    asm("mov.b64 %0, {%1, %2};" : "=l"(r) : "f"(lo), "f"(hi));
    return r;
}
__device__ __forceinline__ float2 unpack2(u64 v) {
    float2 r;
    asm("mov.b64 {%0, %1}, %2;" : "=f"(r.x), "=f"(r.y) : "l"(v));
    return r;
}
__device__ __forceinline__ void red_f32(float* addr, float v) {
    asm volatile("red.global.add.f32 [%0], %1;" :: "l"(addr), "f"(v) : "memory");
}
__device__ __forceinline__ void red_add_v4(float* addr, float a, float b, float c, float d) {
    asm volatile("red.global.add.v4.f32 [%0], {%1,%2,%3,%4};"
                 :: "l"(addr), "f"(a), "f"(b), "f"(c), "f"(d) : "memory");
}

// ---------------- CSR build (+ per-graph node counts), int4 edge reads ----------------
__global__ void k_deg(const int* __restrict__ dst, const int* __restrict__ batch, int e) {
    int i = blockIdx.x * blockDim.x + threadIdx.x;
    int e4 = e >> 2;
    if (i < e4) {
        int4 d4 = ((const int4*)dst)[i];
        atomicAdd(&g_deg[d4.x], 1);
        atomicAdd(&g_deg[d4.y], 1);
        atomicAdd(&g_deg[d4.z], 1);
        atomicAdd(&g_deg[d4.w], 1);
    } else if (i == e4) {
        for (int k = e4 * 4; k < e; ++k) atomicAdd(&g_deg[dst[k]], 1);
    }
    if (i < NNODES) {
        int g = batch[i];
        unsigned act = __activemask();
        unsigned mask = __match_any_sync(act, g);
        int leader = __ffs(mask) - 1;
        if ((threadIdx.x & 31) == leader) atomicAdd(&g_cntg[g], (float)__popc(mask));
    }
}

__global__ void k_chunks() {
    __shared__ int s[512];
    int tid = threadIdx.x;
    int i = blockIdx.x * 512 + tid;
    s[tid] = (i < NNODES) ? g_deg[i] : 0;
    __syncthreads();
    for (int off = 256; off > 0; off >>= 1) {
        if (tid < off) s[tid] += s[tid + off];
        __syncthreads();
    }
    if (tid == 0) g_bsum[blockIdx.x] = s[0];
}

__global__ void k_scan() {
    __shared__ int sb[256];
    __shared__ int s[512];
    int tid = threadIdx.x;
    if (tid < 256) sb[tid] = (tid < NCHUNK) ? g_bsum[tid] : 0;
    int i = blockIdx.x * 512 + tid;
    int v = (i < NNODES) ? g_deg[i] : 0;
    s[tid] = v;
    __syncthreads();
    for (int off = 1; off < 256; off <<= 1) {
        int t = 0;
        if (tid < 256 && tid >= off) t = sb[tid - off];
        __syncthreads();
        if (tid < 256) sb[tid] += t;
        __syncthreads();
    }
    for (int off = 1; off < 512; off <<= 1) {
        int t = (tid >= off) ? s[tid - off] : 0;
        __syncthreads();
        s[tid] += t;
        __syncthreads();
    }
    if (i < NNODES) {
        int base = (blockIdx.x > 0) ? sb[blockIdx.x - 1] : 0;
        int r = base + s[tid] - v;
        g_roff[i] = r;
        g_cur[i]  = r;
    }
}

__global__ void k_fill(const int* __restrict__ src, const int* __restrict__ dst, int e) {
    int i = blockIdx.x * blockDim.x + threadIdx.x;
    int e4 = e >> 2;
    if (i < e4) {
        int4 d4 = ((const int4*)dst)[i];
        int4 s4 = ((const int4*)src)[i];
        g_csr[atomicAdd(&g_cur[d4.x], 1)] = s4.x;
        g_csr[atomicAdd(&g_cur[d4.y], 1)] = s4.y;
        g_csr[atomicAdd(&g_cur[d4.z], 1)] = s4.z;
        g_csr[atomicAdd(&g_cur[d4.w], 1)] = s4.w;
    } else if (i == e4) {
        for (int k = e4 * 4; k < e; ++k)
            g_csr[atomicAdd(&g_cur[dst[k]], 1)] = src[k];
    }
}

// ---------------- layer 1: 2 -> 32, thread/node, stats fused, pipelined gather ----------------
__global__ __launch_bounds__(256) void k_layer1(const float* __restrict__ x,
                                                const float* __restrict__ Wl,
                                                const float* __restrict__ bl,
                                                const float* __restrict__ Wr,
                                                float* __restrict__ gsum, float* __restrict__ gsq) {
    __shared__ float sWl[64], sWr[64], sbl[32];
    __shared__ float sRed[512];
    int tid = threadIdx.x, lane = tid & 31, w = tid >> 5;
    if (tid < 64) { sWl[tid] = Wl[tid]; sWr[tid] = Wr[tid]; }
    if (tid < 32) sbl[tid] = bl[tid];
    __syncthreads();
    int n = blockIdx.x * 256 + tid;
    bool active = (n < NNODES);
    const float2* x2 = (const float2*)x;
    float a0 = 0.f, a1 = 0.f;
    float2 xv = make_float2(0.f, 0.f);
    if (active) {
        int st = g_roff[n], d = g_deg[n];
        int k = 0;
        int si[8];
        if (d >= 8) {
#pragma unroll
            for (int j = 0; j < 8; j++) si[j] = g_csr[st + j];
        }
        while (k + 8 <= d) {
            int kn = k + 8;
            bool more = (kn + 8 <= d);
            int sn[8];
#pragma unroll
            for (int j = 0; j < 8; j++) sn[j] = more ? g_csr[st + kn + j] : 0;
            float2 v[8];
#pragma unroll
            for (int j = 0; j < 8; j++) v[j] = x2[si[j]];
#pragma unroll
            for (int j = 0; j < 8; j++) { a0 += v[j].x; a1 += v[j].y; }
#pragma unroll
            for (int j = 0; j < 8; j++) si[j] = sn[j];
            k = kn;
        }
        for (; k < d; ++k) { float2 v = x2[g_csr[st + k]]; a0 += v.x; a1 += v.y; }
        float inv = 1.f / (float)max(d, 1);
        a0 *= inv; a1 *= inv;
        xv = x2[n];
    }
    float z[32];
#pragma unroll
    for (int j = 0; j < 32; j++)
        z[j] = active ? (sbl[j] + a0 * sWl[j] + a1 * sWl[32 + j] + xv.x * sWr[j] + xv.y * sWr[32 + j]) : 0.f;
    if (active) {
        float* outp = &g_h1[n * 32];
#pragma unroll
        for (int j = 0; j < 32; j += 4)
            *(float4*)&outp[j] = make_float4(z[j], z[j + 1], z[j + 2], z[j + 3]);
    }
    float ws = 0.f, wq = 0.f;
#pragma unroll
    for (int c = 0; c < 32; c++) {
        float s = z[c];
        float q = z[c] * z[c];
#pragma unroll
        for (int o = 16; o; o >>= 1) {
            s += __shfl_xor_sync(0xffffffffu, s, o);
            q += __shfl_xor_sync(0xffffffffu, q, o);
        }
        if (lane == c) { ws = s; wq = q; }
    }
    sRed[w * 64 + lane]      = ws;
    sRed[w * 64 + 32 + lane] = wq;
    __syncthreads();
    if (tid < 64) {
        int c = tid & 31;
        int off = (tid >= 32) ? 32 : 0;
        float a = 0.f;
#pragma unroll
        for (int w2 = 0; w2 < 8; w2++) a += sRed[w2 * 64 + off + c];
        red_f32((tid >= 32) ? &gsq[c] : &gsum[c], a);
    }
}

// ---------------- layer 2: 32 -> 64; BN1+relu fused; pipelined gather; stats fused ----------------
__global__ __launch_bounds__(256) void k_layer2(const float* __restrict__ Wl,
                                                const float* __restrict__ bl,
                                                const float* __restrict__ Wr,
                                                const float* __restrict__ st1,   // sum@0, sq@32
                                                const float* __restrict__ gam, const float* __restrict__ bet,
                                                float* __restrict__ gsum, float* __restrict__ gsq) {
    __shared__ float sWl[2048], sWr[2048], sbl[64];
    __shared__ float sSc[32], sSh[32];
    __shared__ float sAX[64 * 64];
    int tid = threadIdx.x, lane = tid & 31, w = tid >> 5;
    for (int i = tid; i < 2048; i += 256) { sWl[i] = Wl[i]; sWr[i] = Wr[i]; }
    if (tid < 64) sbl[tid] = bl[tid];
    if (tid < 32) {
        float mean = st1[tid] * (1.f / NNODES);
        float var  = st1[32 + tid] * (1.f / NNODES) - mean * mean;
        float sc = gam[tid] * rsqrtf(var + EPS);
        sSc[tid] = sc;
        sSh[tid] = bet[tid] - mean * sc;
    }
    __syncthreads();
    float sc = sSc[lane], sh = sSh[lane];
    int base = blockIdx.x * 64;
    for (int r = 0; r < 8; r++) {
        int rr = w * 8 + r;
        int node = base + rr;
        float2 axv = make_float2(0.f, 0.f);
        if (node < NNODES) {
            int st = g_roff[node], d = g_deg[node];
            float acc = 0.f;
            int k = 0;
            int si[8];
            if (d >= 8) {
#pragma unroll
                for (int j = 0; j < 8; j++) si[j] = g_csr[st + j];
            }
            while (k + 8 <= d) {
                int kn = k + 8;
                bool more = (kn + 8 <= d);
                int sn[8];
#pragma unroll
                for (int j = 0; j < 8; j++) sn[j] = more ? g_csr[st + kn + j] : 0;
                float v[8];
#pragma unroll
                for (int j = 0; j < 8; j++) v[j] = g_h1[si[j] * 32 + lane];
#pragma unroll
                for (int j = 0; j < 8; j++) acc += fmaxf(fmaf(v[j], sc, sh), 0.f);
#pragma unroll
                for (int j = 0; j < 8; j++) si[j] = sn[j];
                k = kn;
            }
            for (; k < d; ++k) acc += fmaxf(fmaf(g_h1[g_csr[st + k] * 32 + lane], sc, sh), 0.f);
            axv.x = acc * (1.f / (float)max(d, 1));
            axv.y = fmaxf(fmaf(g_h1[node * 32 + lane], sc, sh), 0.f);
        }
        *(float2*)&sAX[rr * 64 + 2 * lane] = axv;
    }
    __syncthreads();
    u64 acc[8];
    {
        u64 b = *(const u64*)&sbl[2 * lane];
#pragma unroll
        for (int r = 0; r < 8; r++) acc[r] = b;
    }
#pragma unroll 4
    for (int i = 0; i < 32; i++) {
        u64 wl = *(const u64*)&sWl[i * 64 + 2 * lane];
        u64 wr = *(const u64*)&sWr[i * 64 + 2 * lane];
#pragma unroll
        for (int r = 0; r < 8; r++) {
            float2 ax = *(const float2*)&sAX[(w * 8 + r) * 64 + 2 * i];
            acc[r] = ffma2(pack2(ax.x, ax.x), wl, acc[r]);
            acc[r] = ffma2(pack2(ax.y, ax.y), wr, acc[r]);
        }
    }
    float s0 = 0.f, s1 = 0.f, q0 = 0.f, q1 = 0.f;
#pragma unroll
    for (int r = 0; r < 8; r++) {
        int node = base + w * 8 + r;
        if (node < NNODES) {
            float2 v = unpack2(acc[r]);
            *(float2*)&g_h2[node * 64 + 2 * lane] = v;
            s0 += v.x; s1 += v.y; q0 += v.x * v.x; q1 += v.y * v.y;
        }
    }
    __syncthreads();
    float* sRed = sAX;
    sRed[w * 128 + 2 * lane]     = s0;
    sRed[w * 128 + 2 * lane + 1] = s1;
    sRed[w * 128 + 64 + 2 * lane]     = q0;
    sRed[w * 128 + 64 + 2 * lane + 1] = q1;
    __syncthreads();
    if (tid < 128) {
        int c = tid & 63;
        int off = (tid >= 64) ? 64 : 0;
        float a = 0.f;
#pragma unroll
        for (int w2 = 0; w2 < 8; w2++) a += sRed[w2 * 128 + off + c];
        red_f32((tid >= 64) ? &gsq[c] : &gsum[c], a);
    }
}

// ---------------- layer 3: 64 -> 128; 128 thr/block, 8 rows/warp, pipelined gather ----------------
__global__ __launch_bounds__(128) void k_layer3(const float* __restrict__ Wl,
                                                const float* __restrict__ bl,
                                                const float* __restrict__ Wr,
                                                const float* __restrict__ st2,   // sum@0, sq@64
                                                const float* __restrict__ gam, const float* __restrict__ bet,
                                                float* __restrict__ gsum, float* __restrict__ gsq) {
    __shared__ float sAX[32 * 128];   // 16 KB; reused for reduce
    __shared__ float sSc[64], sSh[64];
    int tid = threadIdx.x, lane = tid & 31, w = tid >> 5;   // 4 warps
    if (tid < 64) {
        float mean = st2[tid] * (1.f / NNODES);
        float var  = st2[64 + tid] * (1.f / NNODES) - mean * mean;
        float sc = gam[tid] * rsqrtf(var + EPS);
        sSc[tid] = sc;
        sSh[tid] = bet[tid] - mean * sc;
    }
    __syncthreads();
    float sc0 = sSc[2 * lane], sc1 = sSc[2 * lane + 1];
    float sh0 = sSh[2 * lane], sh1 = sSh[2 * lane + 1];
    int base = blockIdx.x * 32;
    const float2* h2v = (const float2*)g_h2;
    for (int r = 0; r < 8; r++) {
        int rr = w * 8 + r;
        int node = base + rr;
        float4 axv = make_float4(0.f, 0.f, 0.f, 0.f);
        if (node < NNODES) {
            int st = g_roff[node], d = g_deg[node];
            float a0 = 0.f, a1 = 0.f;
            int k = 0;
            int si[8];
            if (d >= 8) {
#pragma unroll
                for (int j = 0; j < 8; j++) si[j] = g_csr[st + j];
            }
            while (k + 8 <= d) {
                int kn = k + 8;
                bool more = (kn + 8 <= d);
                int sn[8];
#pragma unroll
                for (int j = 0; j < 8; j++) sn[j] = more ? g_csr[st + kn + j] : 0;
                float2 v[8];
#pragma unroll
                for (int j = 0; j < 8; j++) v[j] = h2v[si[j] * 32 + lane];
#pragma unroll
                for (int j = 0; j < 8; j++) {
                    a0 += fmaxf(fmaf(v[j].x, sc0, sh0), 0.f);
                    a1 += fmaxf(fmaf(v[j].y, sc1, sh1), 0.f);
                }
#pragma unroll
                for (int j = 0; j < 8; j++) si[j] = sn[j];
                k = kn;
            }
            for (; k < d; ++k) {
                float2 v = h2v[g_csr[st + k] * 32 + lane];
                a0 += fmaxf(fmaf(v.x, sc0, sh0), 0.f);
                a1 += fmaxf(fmaf(v.y, sc1, sh1), 0.f);
            }
            float inv = 1.f / (float)max(d, 1);
            float2 hx = h2v[node * 32 + lane];
            axv = make_float4(a0 * inv,
                              fmaxf(fmaf(hx.x, sc0, sh0), 0.f),
                              a1 * inv,
                              fmaxf(fmaf(hx.y, sc1, sh1), 0.f));
        }
        *(float4*)&sAX[rr * 128 + 4 * lane] = axv;
    }
    __syncthreads();
    const ulonglong2* Wl2 = (const ulonglong2*)Wl;
    const ulonglong2* Wr2 = (const ulonglong2*)Wr;
    u64 a01[8], a23[8];
    {
        ulonglong2 b2 = __ldg((const ulonglong2*)bl + lane);
#pragma unroll
        for (int r = 0; r < 8; r++) { a01[r] = b2.x; a23[r] = b2.y; }
    }
#pragma unroll 2
    for (int i = 0; i < 64; i++) {
        ulonglong2 wl = __ldg(Wl2 + i * 32 + lane);
        ulonglong2 wr = __ldg(Wr2 + i * 32 + lane);
#pragma unroll
        for (int r = 0; r < 8; r++) {
            float2 ax = *(const float2*)&sAX[(w * 8 + r) * 128 + 2 * i];
            u64 A = pack2(ax.x, ax.x);
            u64 X = pack2(ax.y, ax.y);
            a01[r] = ffma2(A, wl.x, a01[r]);
            a23[r] = ffma2(A, wl.y, a23[r]);
            a01[r] = ffma2(X, wr.x, a01[r]);
            a23[r] = ffma2(X, wr.y, a23[r]);
        }
    }
    float s[4] = {0.f, 0.f, 0.f, 0.f}, q[4] = {0.f, 0.f, 0.f, 0.f};
#pragma unroll
    for (int r = 0; r < 8; r++) {
        int node = base + w * 8 + r;
        if (node < NNODES) {
            float2 v01 = unpack2(a01[r]);
            float2 v23 = unpack2(a23[r]);
            *(float4*)&g_h3[(size_t)node * 128 + 4 * lane] = make_float4(v01.x, v01.y, v23.x, v23.y);
            s[0] += v01.x; s[1] += v01.y; s[2] += v23.x; s[3] += v23.y;
            q[0] += v01.x * v01.x; q[1] += v01.y * v01.y; q[2] += v23.x * v23.x; q[3] += v23.y * v23.y;
        }
    }
    __syncthreads();
    float* sRed = sAX;   // 4 warps × 256 floats = 1024 <= 4096
#pragma unroll
    for (int k = 0; k < 4; k++) {
        sRed[w * 256 + 4 * lane + k]       = s[k];
        sRed[w * 256 + 128 + 4 * lane + k] = q[k];
    }
    __syncthreads();
    {
        int c = tid;
        float a = 0.f, b = 0.f;
#pragma unroll
        for (int w2 = 0; w2 < 4; w2++) {
            a += sRed[w2 * 256 + c];
            b += sRed[w2 * 256 + 128 + c];
        }
        red_f32(&gsum[c], a);
        red_f32(&gsq[c], b);
    }
}

// ---------------- fused finalize3 + bn + relu + pool (8-row local accumulation) ----------------
__global__ __launch_bounds__(256) void k_bnpool(const int* __restrict__ batch,
                                                const float* __restrict__ gsum, const float* __restrict__ gsq,
                                                const float* __restrict__ gam, const float* __restrict__ bet) {
    __shared__ float ssc[128], ssh[128];
    int tid = threadIdx.x;
    if (tid < 128) {
        float mean = gsum[tid] * (1.f / NNODES);
        float var  = gsq[tid] * (1.f / NNODES) - mean * mean;
        float sc = gam[tid] * rsqrtf(var + EPS);
        ssc[tid] = sc;
        ssh[tid] = bet[tid] - mean * sc;
    }
    __syncthreads();
    int c4 = tid & 31;              // float4 column
    int rgrp = tid >> 5;            // 0..7
    int row0 = blockIdx.x * 64 + rgrp * 8;
    int c = c4 * 4;
    float4 sc = *(const float4*)&ssc[c];
    float4 sh = *(const float4*)&ssh[c];
    float4 acc = make_float4(0.f, 0.f, 0.f, 0.f);
    int curg = -1;
    const float4* h3v = (const float4*)g_h3;
#pragma unroll
    for (int j = 0; j < 8; j++) {
        int row = row0 + j;
        if (row >= NNODES) break;
        int g = batch[row];
        if (g != curg) {
            if (curg >= 0) red_add_v4(&g_pool[curg * 128 + c], acc.x, acc.y, acc.z, acc.w);
            acc = make_float4(0.f, 0.f, 0.f, 0.f);
            curg = g;
        }
        float4 v = h3v[(size_t)row * 32 + c4];
        acc.x += fmaxf(v.x * sc.x + sh.x, 0.f);
        acc.y += fmaxf(v.y * sc.y + sh.y, 0.f);
        acc.z += fmaxf(v.z * sc.z + sh.z, 0.f);
        acc.w += fmaxf(v.w * sc.w + sh.w, 0.f);
    }
    if (curg >= 0) red_add_v4(&g_pool[curg * 128 + c], acc.x, acc.y, acc.z, acc.w);
}

// ---------------- head MLP ----------------
__global__ void k_mlp(const float* __restrict__ Wf1, const float* __restrict__ bf1,
                      const float* __restrict__ Wf2, const float* __restrict__ bf2,
                      float* __restrict__ out) {
    __shared__ float sp[128];
    __shared__ float sh[64];
    int g = blockIdx.x, tid = threadIdx.x;
    float inv = 1.f / fmaxf(g_cntg[g], 1.f);
    sp[tid] = g_pool[g * 128 + tid] * inv;
    __syncthreads();
    if (tid < 64) {
        float acc = bf1[tid];
#pragma unroll 8
        for (int i = 0; i < 128; i++) acc += sp[i] * Wf1[i * 64 + tid];
        acc = fmaxf(acc, 0.f);
        sh[tid] = acc * Wf2[tid];
    }
    __syncthreads();
    if (tid < 32) {
        float v = sh[tid] + sh[tid + 32];
        for (int o = 16; o; o >>= 1) v += __shfl_down_sync(0xffffffffu, v, o);
        if (tid == 0) out[g] = v + bf2[0];
    }
}

// ---------------- launch ----------------
extern "C" void kernel_launch(void* const* d_in, const int* in_sizes, int n_in,
                              void* d_out, int out_size) {
    const float* x     = (const float*)d_in[0];
    const int*   ei    = (const int*)d_in[1];
    const int*   batch = (const int*)d_in[2];
    const float* Wl1 = (const float*)d_in[3];
    const float* bl1 = (const float*)d_in[4];
    const float* Wr1 = (const float*)d_in[5];
    const float* g1  = (const float*)d_in[6];
    const float* be1 = (const float*)d_in[7];
    const float* Wl2 = (const float*)d_in[8];
    const float* bl2 = (const float*)d_in[9];
    const float* Wr2 = (const float*)d_in[10];
    const float* g2  = (const float*)d_in[11];
    const float* be2 = (const float*)d_in[12];
    const float* Wl3 = (const float*)d_in[13];
    const float* bl3 = (const float*)d_in[14];
    const float* Wr3 = (const float*)d_in[15];
    const float* g3  = (const float*)d_in[16];
    const float* be3 = (const float*)d_in[17];
    const float* Wf1 = (const float*)d_in[18];
    const float* bf1 = (const float*)d_in[19];
    const float* Wf2 = (const float*)d_in[20];
    const float* bf2 = (const float*)d_in[21];

    int E = in_sizes[1] / 2;
    const int* src = ei;
    const int* dst = ei + E;

    void *p_stats, *p_deg, *p_pool, *p_cnt;
    cudaGetSymbolAddress(&p_stats, g_stats);
    cudaGetSymbolAddress(&p_deg,   g_deg);
    cudaGetSymbolAddress(&p_pool,  g_pool);
    cudaGetSymbolAddress(&p_cnt,   g_cntg);
    float* st = (float*)p_stats;

    int e4b = (E / 4 + 256) / 256;         // covers e4 threads + tail thread; also >= NNODES/256
    if (e4b < (NNODES + 255) / 256) e4b = (NNODES + 255) / 256;
    const int NB = (NNODES + 255) / 256;   // 391
    const int GB2 = (NNODES + 63) / 64;    // 1563
    const int GB3 = (NNODES + 31) / 32;    // 3125 (128-thread blocks)

    cudaMemsetAsync(p_deg,   0, NNODES * sizeof(int));
    cudaMemsetAsync(p_stats, 0, 448 * sizeof(float));
    cudaMemsetAsync(p_pool,  0, NGRAPHS * 128 * sizeof(float));
    cudaMemsetAsync(p_cnt,   0, NGRAPHS * sizeof(float));

    k_deg<<<e4b, 256>>>(dst, batch, E);
    k_chunks<<<NCHUNK, 512>>>();
    k_scan<<<NCHUNK, 512>>>();
    k_fill<<<e4b, 256>>>(src, dst, E);

    // layer 1 (stats fused, pipelined gather)
    k_layer1<<<NB, 256>>>(x, Wl1, bl1, Wr1, st + 0, st + 32);

    // layer 2 (BN1+relu fused, pipelined gather, stats fused)
    k_layer2<<<GB2, 256>>>(Wl2, bl2, Wr2, st + 0, g1, be1, st + 64, st + 128);

    // layer 3 (BN2+relu fused, pipelined gather, 8 rows/warp)
    k_layer3<<<GB3, 128>>>(Wl3, bl3, Wr3, st + 64, g2, be2, st + 192, st + 320);

    // fused bn3 + relu + pool (64 rows/block, local accumulation), then head
    k_bnpool<<<(NNODES + 63) / 64, 256>>>(batch, st + 192, st + 320, g3, be3);
    k_mlp<<<NGRAPHS, 128>>>(Wf1, bf1, Wf2, bf2, (float*)d_out);
}